// round 15
// baseline (speedup 1.0000x reference)
#include <cuda_runtime.h>

// TritonDualLIF: x [T=16,B=32,N=196,C=512] f32, decay scalar.
// v = d*v + x[t]; vpool[t,b,c] = mean_n(pre-reset v); s = (v>=1); v = s?0:v.
// out = spikes [T,B,N,C] ++ vpool [T,B,C].
//
// R14 full-row layout (CTA owns all C x 7 consecutive n-rows, dense 14KB
// extents, atomic vpool, no smem/barriers) + TWO-deep timestep prefetch:
// t+1 and t+2 inputs kept in registers -> ~21-28 loads in flight per thread.

#define T_ 16
#define B_ 32
#define N_ 196
#define C_ 512
#define C2 (C_ / 2)        // 256 float2 per row
#define NH 28              // chunks of 7 consecutive rows (28*7 = 196)
#define ROWS 7

__global__ __launch_bounds__(256, 3)
void lif_dual_kernel(const float2* __restrict__ x,
                     const float* __restrict__ decay,
                     float* __restrict__ out) {
    const int tid = threadIdx.x;      // c2 lane 0..255 (full C coverage)
    const int b   = blockIdx.x;       // 0..31
    const int z   = blockIdx.y;       // 0..27 (7-row chunk)
    const float d = decay[0];

    float2* __restrict__ spikes = (float2*)out;
    float*  __restrict__ vpool  = out + (size_t)T_ * B_ * N_ * C_;

    float2 v[ROWS];
    float2 xc[ROWS];   // inputs for t
    float2 xn[ROWS];   // inputs for t+1
#pragma unroll
    for (int j = 0; j < ROWS; ++j) v[j] = make_float2(0.f, 0.f);

    const unsigned bbase   = (unsigned)b * (N_ * C2)
                           + (unsigned)(z * ROWS) * C2 + (unsigned)tid;
    const unsigned tstride = (unsigned)(B_ * N_ * C2);

    float* vp = vpool + (unsigned)b * C_ + (unsigned)tid * 2u;
    const float inv = 1.0f / (float)N_;

    // Prologue: load t=0 and t=1 inputs.
#pragma unroll
    for (int j = 0; j < ROWS; ++j)
        xc[j] = x[bbase + (unsigned)(j * C2)];
#pragma unroll
    for (int j = 0; j < ROWS; ++j)
        xn[j] = x[bbase + tstride + (unsigned)(j * C2)];

    for (int t = 0; t < T_; ++t) {
        const unsigned tb = (unsigned)t * tstride + bbase;

        // Prefetch t+2 before consuming t (2-deep pipeline).
        float2 xnn[ROWS];
        if (t + 2 < T_) {
            const unsigned nb = tb + 2u * tstride;
#pragma unroll
            for (int j = 0; j < ROWS; ++j)
                xnn[j] = x[nb + (unsigned)(j * C2)];
        }

        float2 part = make_float2(0.f, 0.f);
#pragma unroll
        for (int j = 0; j < ROWS; ++j) {
            const unsigned idx = tb + (unsigned)(j * C2);
            float2 vv;
            vv.x = fmaf(d, v[j].x, xc[j].x);
            vv.y = fmaf(d, v[j].y, xc[j].y);
            part.x += vv.x;                   // pre-reset membrane
            part.y += vv.y;
            const bool fx = (vv.x >= 1.0f);
            const bool fy = (vv.y >= 1.0f);
            float2 s;
            s.x = fx ? 1.0f : 0.0f;
            s.y = fy ? 1.0f : 0.0f;
            spikes[idx] = s;
            v[j].x = fx ? 0.0f : vv.x;        // hard reset
            v[j].y = fy ? 0.0f : vv.y;
        }

        // Accumulate this chunk's 7-row partial into vpool (28 adds/output).
        float* vpt = vp + (unsigned)t * (B_ * C_);
        atomicAdd(vpt,     part.x * inv);
        atomicAdd(vpt + 1, part.y * inv);

#pragma unroll
        for (int j = 0; j < ROWS; ++j) { xc[j] = xn[j]; xn[j] = xnn[j]; }
    }
}

extern "C" void kernel_launch(void* const* d_in, const int* in_sizes, int n_in,
                              void* d_out, int out_size) {
    const float2* x    = (const float2*)d_in[0];
    const float* decay = (const float*)d_in[1];
    float* out = (float*)d_out;

    // Zero the vpool region (accumulated atomically by the kernel).
    float* vpool = out + (size_t)T_ * B_ * N_ * C_;
    cudaMemsetAsync(vpool, 0, (size_t)T_ * B_ * C_ * sizeof(float));

    dim3 block(256);
    dim3 grid(B_, NH);                  // 32 x 28 = 896 CTAs
    lif_dual_kernel<<<grid, block>>>(x, decay, out);
}

// round 16
// speedup vs baseline: 1.0119x; 1.0119x over previous
#include <cuda_runtime.h>

// TritonDualLIF: x [T=16,B=32,N=196,C=512] f32, decay scalar.
// v = d*v + x[t]; vpool[t,b,c] = mean_n(pre-reset v); s = (v>=1); v = s?0:v.
// out = spikes [T,B,N,C] ++ vpool [T,B,C].
//
// R15 body (full-row dense extents, 2-deep timestep prefetch, atomic vpool,
// no smem/barriers) with launch_bounds(256,4): at the 56 regs ptxas already
// chose, a 4th resident CTA/SM fits for free (+33% latency tolerance).

#define T_ 16
#define B_ 32
#define N_ 196
#define C_ 512
#define C2 (C_ / 2)        // 256 float2 per row
#define NH 28              // chunks of 7 consecutive rows (28*7 = 196)
#define ROWS 7

__global__ __launch_bounds__(256, 4)
void lif_dual_kernel(const float2* __restrict__ x,
                     const float* __restrict__ decay,
                     float* __restrict__ out) {
    const int tid = threadIdx.x;      // c2 lane 0..255 (full C coverage)
    const int b   = blockIdx.x;       // 0..31
    const int z   = blockIdx.y;       // 0..27 (7-row chunk)
    const float d = decay[0];

    float2* __restrict__ spikes = (float2*)out;
    float*  __restrict__ vpool  = out + (size_t)T_ * B_ * N_ * C_;

    float2 v[ROWS];
    float2 xc[ROWS];   // inputs for t
    float2 xn[ROWS];   // inputs for t+1
#pragma unroll
    for (int j = 0; j < ROWS; ++j) v[j] = make_float2(0.f, 0.f);

    const unsigned bbase   = (unsigned)b * (N_ * C2)
                           + (unsigned)(z * ROWS) * C2 + (unsigned)tid;
    const unsigned tstride = (unsigned)(B_ * N_ * C2);

    float* vp = vpool + (unsigned)b * C_ + (unsigned)tid * 2u;
    const float inv = 1.0f / (float)N_;

    // Prologue: load t=0 and t=1 inputs.
#pragma unroll
    for (int j = 0; j < ROWS; ++j)
        xc[j] = x[bbase + (unsigned)(j * C2)];
#pragma unroll
    for (int j = 0; j < ROWS; ++j)
        xn[j] = x[bbase + tstride + (unsigned)(j * C2)];

    for (int t = 0; t < T_; ++t) {
        const unsigned tb = (unsigned)t * tstride + bbase;

        // Prefetch t+2 before consuming t (2-deep pipeline).
        float2 xnn[ROWS];
        if (t + 2 < T_) {
            const unsigned nb = tb + 2u * tstride;
#pragma unroll
            for (int j = 0; j < ROWS; ++j)
                xnn[j] = x[nb + (unsigned)(j * C2)];
        }

        float2 part = make_float2(0.f, 0.f);
#pragma unroll
        for (int j = 0; j < ROWS; ++j) {
            const unsigned idx = tb + (unsigned)(j * C2);
            float2 vv;
            vv.x = fmaf(d, v[j].x, xc[j].x);
            vv.y = fmaf(d, v[j].y, xc[j].y);
            part.x += vv.x;                   // pre-reset membrane
            part.y += vv.y;
            const bool fx = (vv.x >= 1.0f);
            const bool fy = (vv.y >= 1.0f);
            float2 s;
            s.x = fx ? 1.0f : 0.0f;
            s.y = fy ? 1.0f : 0.0f;
            spikes[idx] = s;
            v[j].x = fx ? 0.0f : vv.x;        // hard reset
            v[j].y = fy ? 0.0f : vv.y;
        }

        // Accumulate this chunk's 7-row partial into vpool (28 adds/output).
        float* vpt = vp + (unsigned)t * (B_ * C_);
        atomicAdd(vpt,     part.x * inv);
        atomicAdd(vpt + 1, part.y * inv);

#pragma unroll
        for (int j = 0; j < ROWS; ++j) { xc[j] = xn[j]; xn[j] = xnn[j]; }
    }
}

extern "C" void kernel_launch(void* const* d_in, const int* in_sizes, int n_in,
                              void* d_out, int out_size) {
    const float2* x    = (const float2*)d_in[0];
    const float* decay = (const float*)d_in[1];
    float* out = (float*)d_out;

    // Zero the vpool region (accumulated atomically by the kernel).
    float* vpool = out + (size_t)T_ * B_ * N_ * C_;
    cudaMemsetAsync(vpool, 0, (size_t)T_ * B_ * C_ * sizeof(float));

    dim3 block(256);
    dim3 grid(B_, NH);                  // 32 x 28 = 896 CTAs
    lif_dual_kernel<<<grid, block>>>(x, decay, out);
}